// round 12
// baseline (speedup 1.0000x reference)
#include <cuda_runtime.h>
#include <cuda_fp16.h>

#define NV 256
#define MANG 180
#define PIDX(j) ((j) + ((j) >> 3))

// Scratch (static device globals — no runtime allocation)
__device__ __half2 g_Fh[NV * NV * NV];      // ping (67 MB)
__device__ __half2 g_F2h[NV * NV * NV];     // pong (67 MB)
__device__ __half2 g_Sh[MANG * NV * NV];    // slice intermediate T[m][iu][ka]

__device__ __forceinline__ float2 cmulf(float2 a, float2 b) {
    return make_float2(a.x * b.x - a.y * b.y, a.x * b.y + a.y * b.x);
}
__device__ __forceinline__ float2 u2f2(unsigned u) {
    __half2 h = *reinterpret_cast<__half2*>(&u);
    return __half22float2(h);
}
__device__ __forceinline__ unsigned f2u(float2 v) {
    __half2 h = __floats2half2_rn(v.x, v.y);
    return *reinterpret_cast<unsigned*>(&h);
}

// ---------------------------------------------------------------------------
// 256-pt FFT core: 8 regs/lane. radix-2^3 in regs + twiddle + radix-32 shuffle.
// On exit reg r, lane holds bin k = brev3(r) + 8*brev5(lane).
// ---------------------------------------------------------------------------
template <int SIGN>
__device__ __forceinline__ void fft_core(float2 x[8], int lane, const float2* tw) {
    const float SG = (float)SIGN;
    const float C7 = 0.70710678118654752f;
#define BTF(A, B, TR, TI_)                                         \
    {                                                              \
        float dr = (A).x - (B).x, di = (A).y - (B).y;              \
        (A).x += (B).x; (A).y += (B).y;                            \
        (B).x = dr * (TR) - di * (TI_);                            \
        (B).y = dr * (TI_) + di * (TR);                            \
    }
    BTF(x[0], x[4], 1.0f, 0.0f);
    BTF(x[1], x[5], C7, SG * C7);
    BTF(x[2], x[6], 0.0f, SG);
    BTF(x[3], x[7], -C7, SG * C7);
    BTF(x[0], x[2], 1.0f, 0.0f);
    BTF(x[1], x[3], 0.0f, SG);
    BTF(x[4], x[6], 1.0f, 0.0f);
    BTF(x[5], x[7], 0.0f, SG);
    BTF(x[0], x[1], 1.0f, 0.0f);
    BTF(x[2], x[3], 1.0f, 0.0f);
    BTF(x[4], x[5], 1.0f, 0.0f);
    BTF(x[6], x[7], 1.0f, 0.0f);
#undef BTF
    const int k1tab[8] = {0, 4, 2, 6, 1, 5, 3, 7};
#pragma unroll
    for (int r = 1; r < 8; r++)
        x[r] = cmulf(x[r], tw[(lane * k1tab[r]) & 255]);
#pragma unroll
    for (int s = 4; s >= 0; s--) {
        const int h = 1 << s;
        const int j = lane & (h - 1);
        const float2 w = tw[j << (7 - s)];
        const bool hi = (lane & h) != 0;
#pragma unroll
        for (int r = 0; r < 8; r++) {
            float2 o;
            o.x = __shfl_xor_sync(0xffffffffu, x[r].x, h);
            o.y = __shfl_xor_sync(0xffffffffu, x[r].y, h);
            if (hi) {
                float2 d = make_float2(o.x - x[r].x, o.y - x[r].y);
                x[r] = cmulf(d, w);
            } else {
                x[r].x += o.x;
                x[r].y += o.y;
            }
        }
    }
}

// ---------------------------------------------------------------------------
// Pass 1: contiguous z-axis forward FFT. Direct coalesced register loads,
// shared staging on store side only. fp16 out, band-filtered z.
// launch_bounds(256,6): +20% resident warps to hide streaming load latency.
// ---------------------------------------------------------------------------
__global__ void __launch_bounds__(256, 6) fft256_p1(const float2* __restrict__ in,
                                                    __half2* __restrict__ out,
                                                    const float* tilt) {
    __shared__ float2 sm[8][288];
    __shared__ float2 tw[256];
    const int tid  = threadIdx.x;
    const int warp = tid >> 5;
    const int lane = tid & 31;
    const unsigned base = blockIdx.x * 2048u;

    float a = 128.0f * fabsf(sinf(*tilt));
    const int zlo = (int)floorf(126.0f - a);
    const int zhi = (int)ceilf(130.0f + a);

    {
        float s, c;
        sincospif((float)tid * (1.0f / 128.0f), &s, &c);
        tw[tid] = make_float2(c, -s);   // SIGN = -1
    }
    __syncthreads();

    float2 x[8];
    const float insgn = (lane & 1) ? -1.0f : 1.0f;
    {
        const float2* ip = in + base + (unsigned)warp * 256u;
#pragma unroll
        for (int r = 0; r < 8; r++) {
            float2 v = __ldg(ip + r * 32 + lane);
            x[r] = make_float2(v.x * insgn, v.y * insgn);
        }
    }
    fft_core<-1>(x, lane, tw);

    const int k1tab[8] = {0, 4, 2, 6, 1, 5, 3, 7};
    const int p = (int)(__brev((unsigned)lane) >> 27);
#pragma unroll
    for (int r = 0; r < 8; r++) {
        int k = k1tab[r] + 8 * p;
        float sg = ((r >> 2) & 1) ? -1.0f : 1.0f;
        sm[warp][PIDX(k)] = make_float2(x[r].x * sg, x[r].y * sg);
    }
    __syncthreads();
#pragma unroll
    for (int idx = tid; idx < 1024; idx += 256) {
        int line = idx >> 7;
        int k = (idx & 127) * 2;
        if (k + 1 >= zlo && k <= zhi) {
            uint2 st = make_uint2(f2u(sm[line][PIDX(k)]), f2u(sm[line][PIDX(k + 1)]));
            *(uint2*)(out + base + (unsigned)line * 256u + k) = st;
        }
    }
}

// ---------------------------------------------------------------------------
// Strided fp16->fp16 pass: 16 lines/block, raw-uint fp16 smem staging
// (19.4 KB — required so 6 blocks/SM fit in smem). Block-level ZFILT.
// launch_bounds(256,6): regs capped 42 -> 6 blocks/SM instead of 5.
// ---------------------------------------------------------------------------
template <int SIGN>
__global__ void __launch_bounds__(256, 6) fft256h16(const __half2* __restrict__ in,
                                                    __half2* __restrict__ out,
                                                    int lsi, const float* tilt) {
    __shared__ unsigned sm[256 * 17];
    __shared__ float2 tw[256];
    const int tid  = threadIdx.x;
    const int warp = tid >> 5;
    const int lane = tid & 31;
    const unsigned l0 = blockIdx.x * 16u;

    {
        float a = 128.0f * fabsf(sinf(*tilt));
        int zlo = (int)floorf(126.0f - a);
        int zhi = (int)ceilf(130.0f + a);
        int z0 = (int)(l0 & 255u);
        if (z0 > zhi || z0 + 15 < zlo) return;
    }

    {
        float s, c;
        sincospif((float)tid * (1.0f / 128.0f), &s, &c);
        tw[tid] = make_float2(c, (float)SIGN * s);
    }

    const unsigned basei = ((l0 >> lsi) << (lsi + 8)) + (l0 & ((1u << lsi) - 1u));
    // staged load: float4 = 4 half2 along b, stored raw (no conversion)
#pragma unroll
    for (int idx = tid; idx < 1024; idx += 256) {
        int bp = idx & 3;
        int j  = idx >> 2;
        int b  = 4 * bp;
        float4 v = *(const float4*)(in + basei + b + ((unsigned)j << lsi));
        const unsigned* u = (const unsigned*)&v;
        int sw = j >> 4;
        int row = j * 17;
#pragma unroll
        for (int i = 0; i < 4; i++)
            sm[row + ((b + i) ^ sw)] = u[i];
    }
    __syncthreads();

    const float insgn = (lane & 1) ? -1.0f : 1.0f;
    const int k1tab[8] = {0, 4, 2, 6, 1, 5, 3, 7};
    const int p = (int)(__brev((unsigned)lane) >> 27);
#pragma unroll
    for (int c = 0; c < 2; c++) {
        const int line = warp + 8 * c;
        float2 x[8];
#pragma unroll
        for (int r = 0; r < 8; r++) {
            int j = r * 32 + lane;
            float2 v = u2f2(sm[j * 17 + (line ^ (j >> 4))]);
            x[r] = make_float2(v.x * insgn, v.y * insgn);
        }
        fft_core<SIGN>(x, lane, tw);
#pragma unroll
        for (int r = 0; r < 8; r++) {
            int k = k1tab[r] + 8 * p;
            float sg = ((r >> 2) & 1) ? -1.0f : 1.0f;
            sm[k * 17 + (line ^ (k >> 4))] = f2u(make_float2(x[r].x * sg, x[r].y * sg));
        }
    }
    __syncthreads();

    // staged store: raw uint copy out
#pragma unroll
    for (int idx = tid; idx < 1024; idx += 256) {
        int bp = idx & 3;
        int k  = idx >> 2;
        int b  = 4 * bp;
        int sw = k >> 4;
        int row = k * 17;
        unsigned u[4];
#pragma unroll
        for (int i = 0; i < 4; i++)
            u[i] = sm[row + ((b + i) ^ sw)];
        *(float4*)(out + basei + b + ((unsigned)k << lsi)) = *(float4*)u;
    }
}

// ---------------------------------------------------------------------------
// Final pass: 16 lines/block, fp16 in, f32 smem, inverse + transposed f32 out.
// launch_bounds(256,6): 6 x 36.8KB = 221KB smem fits; regs capped 42.
// ---------------------------------------------------------------------------
__global__ void __launch_bounds__(256, 6) fft256_fin(const __half2* __restrict__ in,
                                                     float2* __restrict__ out) {
    __shared__ float2 sm[256 * 17];
    __shared__ float2 tw[256];
    const int tid  = threadIdx.x;
    const int warp = tid >> 5;
    const int lane = tid & 31;
    const unsigned l0 = blockIdx.x * 16u;
    const int lsi = 8;

    {
        float s, c;
        sincospif((float)tid * (1.0f / 128.0f), &s, &c);
        tw[tid] = make_float2(c, s);  // SIGN = +1
    }

    const unsigned basei = ((l0 >> lsi) << (lsi + 8)) + (l0 & ((1u << lsi) - 1u));
#pragma unroll
    for (int idx = tid; idx < 1024; idx += 256) {
        int bp = idx & 3;
        int j  = idx >> 2;
        int b  = 4 * bp;
        float4 v = *(const float4*)(in + basei + b + ((unsigned)j << lsi));
        const unsigned* u = (const unsigned*)&v;
        int sw = j >> 4;
        int row = j * 17;
#pragma unroll
        for (int i = 0; i < 4; i++)
            sm[row + ((b + i) ^ sw)] = u2f2(u[i]);
    }
    __syncthreads();

    const float scale = 1.0f / 256.0f;
    const float insgn = (lane & 1) ? -1.0f : 1.0f;
    const int k1tab[8] = {0, 4, 2, 6, 1, 5, 3, 7};
    const int p = (int)(__brev((unsigned)lane) >> 27);
#pragma unroll
    for (int c = 0; c < 2; c++) {
        const int line = warp + 8 * c;
        float2 x[8];
#pragma unroll
        for (int r = 0; r < 8; r++) {
            int j = r * 32 + lane;
            float2 v = sm[j * 17 + (line ^ (j >> 4))];
            x[r] = make_float2(v.x * insgn, v.y * insgn);
        }
        fft_core<1>(x, lane, tw);
#pragma unroll
        for (int r = 0; r < 8; r++) {
            int k = k1tab[r] + 8 * p;
            float sg = ((r >> 2) & 1) ? -scale : scale;
            sm[k * 17 + (line ^ (k >> 4))] = make_float2(x[r].x * sg, x[r].y * sg);
        }
    }
    __syncthreads();

    // transposed f32 store: out[line*256 + k], float4 = 2 complex along k
    const unsigned baseo = l0 << 8;
#pragma unroll
    for (int idx = tid; idx < 2048; idx += 256) {
        int kp = idx & 127;
        int b  = idx >> 7;
        int k  = 2 * kp;
        int sw = (k >> 4);
        float2 a = sm[k * 17 + (b ^ sw)];
        float2 c = sm[(k + 1) * 17 + (b ^ sw)];
        *(float4*)(out + baseo + ((unsigned)b << 8) + k) = make_float4(a.x, a.y, c.x, c.y);
    }
}

// ---------------------------------------------------------------------------
// Fused Fourier-slice sampling + centered inverse FFT over iv.
// Warp owns line (m, iu); lanes walk iv (z-contiguous gathers).
// Interior fast path: 8 unpredicated scalar __ldg (proven floor form).
// UNCHANGED — L1-wavefront saturated; spills would add L1 work.
// ---------------------------------------------------------------------------
__global__ void __launch_bounds__(256) sample_fft_kernel(const __half2* __restrict__ F,
                                                         const float* __restrict__ theta,
                                                         const float* __restrict__ tilt,
                                                         __half2* __restrict__ T) {
    __shared__ float2 sm[8][288];
    __shared__ float2 tw[256];
    const int tid  = threadIdx.x;
    const int warp = tid >> 5;
    const int lane = tid & 31;

    {
        float s, c;
        sincospif((float)tid * (1.0f / 128.0f), &s, &c);
        tw[tid] = make_float2(c, s);  // SIGN = +1 (inverse)
    }
    __syncthreads();

    const int lid = blockIdx.x * 8 + warp;
    const int m  = lid >> 8;
    const int iu = lid & 255;

    float st, ct;
    sincosf(theta[m], &st, &ct);
    float sp, cp;
    sincosf(*tilt, &sp, &cp);

    const float u = (float)(iu - 128);
    const float evx = -st * cp, evy = ct * cp, evz = sp;
    const float bx = u * ct + 128.0f;
    const float by = u * st + 128.0f;
    const float bz = 128.0f;

    float2 x[8];
    const float insgn = (lane & 1) ? -1.0f : 1.0f;
#pragma unroll
    for (int r = 0; r < 8; r++) {
        float v = (float)(r * 32 + lane - 128);
        float px = fmaf(v, evx, bx);
        float py = fmaf(v, evy, by);
        float pz = fmaf(v, evz, bz);

        float fx0 = floorf(px), fy0 = floorf(py), fz0 = floorf(pz);
        float fx = px - fx0, fy = py - fy0, fz = pz - fz0;
        int x0 = (int)fx0, y0 = (int)fy0, z0 = (int)fz0;

        float2 acc = make_float2(0.0f, 0.0f);
        bool interior = ((unsigned)x0 <= 254u) && ((unsigned)y0 <= 254u) && ((unsigned)z0 <= 254u);
        bool anyhit = (x0 >= -1) && (x0 <= 255) && (y0 >= -1) && (y0 <= 255) &&
                      (z0 >= -1) && (z0 <= 255);
        if (interior) {
            const __half2* ptr = F + (((unsigned)x0 << 16) + ((unsigned)y0 << 8) + (unsigned)z0);
            float2 c000 = __half22float2(__ldg(ptr));
            float2 c001 = __half22float2(__ldg(ptr + 1));
            float2 c010 = __half22float2(__ldg(ptr + 256));
            float2 c011 = __half22float2(__ldg(ptr + 257));
            float2 c100 = __half22float2(__ldg(ptr + 65536));
            float2 c101 = __half22float2(__ldg(ptr + 65537));
            float2 c110 = __half22float2(__ldg(ptr + 65792));
            float2 c111 = __half22float2(__ldg(ptr + 65793));
            float gx = 1.0f - fx, gy = 1.0f - fy, gz = 1.0f - fz;
            float w00 = gx * gy, w01 = gx * fy, w10 = fx * gy, w11 = fx * fy;
            float w000 = w00 * gz, w001 = w00 * fz;
            float w010 = w01 * gz, w011 = w01 * fz;
            float w100 = w10 * gz, w101 = w10 * fz;
            float w110 = w11 * gz, w111 = w11 * fz;
            acc.x = w000 * c000.x + w001 * c001.x + w010 * c010.x + w011 * c011.x +
                    w100 * c100.x + w101 * c101.x + w110 * c110.x + w111 * c111.x;
            acc.y = w000 * c000.y + w001 * c001.y + w010 * c010.y + w011 * c011.y +
                    w100 * c100.y + w101 * c101.y + w110 * c110.y + w111 * c111.y;
        } else if (anyhit) {
#pragma unroll
            for (int dx = 0; dx < 2; dx++) {
                int X = x0 + dx;
                float wx = dx ? fx : (1.0f - fx);
#pragma unroll
                for (int dy = 0; dy < 2; dy++) {
                    int Y = y0 + dy;
                    float wy = wx * (dy ? fy : (1.0f - fy));
#pragma unroll
                    for (int dz = 0; dz < 2; dz++) {
                        int Z = z0 + dz;
                        float wz = wy * (dz ? fz : (1.0f - fz));
                        if ((unsigned)X < 256u && (unsigned)Y < 256u && (unsigned)Z < 256u) {
                            unsigned off = ((unsigned)X << 16) + ((unsigned)Y << 8) + (unsigned)Z;
                            float2 val = __half22float2(__ldg(&F[off]));
                            acc.x += wz * val.x;
                            acc.y += wz * val.y;
                        }
                    }
                }
            }
        }
        x[r] = make_float2(acc.x * insgn, acc.y * insgn);
    }

    fft_core<1>(x, lane, tw);

    const float scale = 1.0f / 256.0f;
    const int k1tab[8] = {0, 4, 2, 6, 1, 5, 3, 7};
    const int p = (int)(__brev((unsigned)lane) >> 27);
#pragma unroll
    for (int r = 0; r < 8; r++) {
        int k = k1tab[r] + 8 * p;
        float sg = ((r >> 2) & 1) ? -scale : scale;
        sm[warp][PIDX(k)] = make_float2(x[r].x * sg, x[r].y * sg);
    }
    __syncthreads();
    {
        const unsigned base = blockIdx.x * 2048u;
#pragma unroll
        for (int idx = tid; idx < 1024; idx += 256) {
            int line = idx >> 7;
            int k = (idx & 127) * 2;
            uint2 st = make_uint2(f2u(sm[line][PIDX(k)]), f2u(sm[line][PIDX(k + 1)]));
            *(uint2*)(T + base + (unsigned)line * 256u + k) = st;
        }
    }
}

// ---------------------------------------------------------------------------
extern "C" void kernel_launch(void* const* d_in, const int* in_sizes, int n_in,
                              void* d_out, int out_size) {
    const float2* w     = (const float2*)d_in[0];   // (256,256,256,2) f32
    const float*  theta = (const float*)d_in[1];    // (180,)
    const float*  tilt  = (const float*)d_in[2];    // scalar
    float2* out = (float2*)d_out;                   // (180,256,256,2) f32

    __half2 *F, *F2, *S;
    cudaGetSymbolAddress((void**)&F, g_Fh);
    cudaGetSymbolAddress((void**)&F2, g_F2h);
    cudaGetSymbolAddress((void**)&S, g_Sh);

    // Forward centered 3D FFT (ping-pong, fp16 intermediates):
    fft256_p1<<<8192, 256>>>(w, F, tilt);              // z (contig)
    fft256h16<-1><<<4096, 256>>>(F, F2, 8, tilt);      // y (stride 256)
    fft256h16<-1><<<4096, 256>>>(F2, F, 16, tilt);     // x (stride 65536)

    // Fused slice sampling + inverse FFT over iv -> T[m][iu][ka] (fp16)
    sample_fft_kernel<<<(MANG * 256) / 8, 256>>>(F, theta, tilt, S);

    // Inverse FFT over iu (stride 256 in T), transposed f32 store -> out
    fft256_fin<<<(MANG * 256) / 16, 256>>>(S, out);
}

// round 14
// speedup vs baseline: 1.0978x; 1.0978x over previous
#include <cuda_runtime.h>
#include <cuda_fp16.h>

#define NV 256
#define MANG 180
#define PIDX(j) ((j) + ((j) >> 3))

// Scratch (static device globals — no runtime allocation)
__device__ __half2 g_Fh[NV * NV * NV];      // ping (67 MB)
__device__ __half2 g_F2h[NV * NV * NV];     // pong (67 MB)
__device__ __half2 g_Sh[MANG * NV * NV];    // slice intermediate T[m][iu][ka]

__device__ __forceinline__ float2 cmulf(float2 a, float2 b) {
    return make_float2(a.x * b.x - a.y * b.y, a.x * b.y + a.y * b.x);
}
__device__ __forceinline__ float2 u2f2(unsigned u) {
    __half2 h = *reinterpret_cast<__half2*>(&u);
    return __half22float2(h);
}
__device__ __forceinline__ unsigned f2u(float2 v) {
    __half2 h = __floats2half2_rn(v.x, v.y);
    return *reinterpret_cast<unsigned*>(&h);
}

// ---------------------------------------------------------------------------
// 256-pt FFT core: 8 regs/lane. radix-2^3 in regs + twiddle + radix-32 shuffle.
// On exit reg r, lane holds bin k = brev3(r) + 8*brev5(lane).
// ---------------------------------------------------------------------------
template <int SIGN>
__device__ __forceinline__ void fft_core(float2 x[8], int lane, const float2* tw) {
    const float SG = (float)SIGN;
    const float C7 = 0.70710678118654752f;
#define BTF(A, B, TR, TI_)                                         \
    {                                                              \
        float dr = (A).x - (B).x, di = (A).y - (B).y;              \
        (A).x += (B).x; (A).y += (B).y;                            \
        (B).x = dr * (TR) - di * (TI_);                            \
        (B).y = dr * (TI_) + di * (TR);                            \
    }
    BTF(x[0], x[4], 1.0f, 0.0f);
    BTF(x[1], x[5], C7, SG * C7);
    BTF(x[2], x[6], 0.0f, SG);
    BTF(x[3], x[7], -C7, SG * C7);
    BTF(x[0], x[2], 1.0f, 0.0f);
    BTF(x[1], x[3], 0.0f, SG);
    BTF(x[4], x[6], 1.0f, 0.0f);
    BTF(x[5], x[7], 0.0f, SG);
    BTF(x[0], x[1], 1.0f, 0.0f);
    BTF(x[2], x[3], 1.0f, 0.0f);
    BTF(x[4], x[5], 1.0f, 0.0f);
    BTF(x[6], x[7], 1.0f, 0.0f);
#undef BTF
    const int k1tab[8] = {0, 4, 2, 6, 1, 5, 3, 7};
#pragma unroll
    for (int r = 1; r < 8; r++)
        x[r] = cmulf(x[r], tw[(lane * k1tab[r]) & 255]);
#pragma unroll
    for (int s = 4; s >= 0; s--) {
        const int h = 1 << s;
        const int j = lane & (h - 1);
        const float2 w = tw[j << (7 - s)];
        const bool hi = (lane & h) != 0;
#pragma unroll
        for (int r = 0; r < 8; r++) {
            float2 o;
            o.x = __shfl_xor_sync(0xffffffffu, x[r].x, h);
            o.y = __shfl_xor_sync(0xffffffffu, x[r].y, h);
            if (hi) {
                float2 d = make_float2(o.x - x[r].x, o.y - x[r].y);
                x[r] = cmulf(d, w);
            } else {
                x[r].x += o.x;
                x[r].y += o.y;
            }
        }
    }
}

// ---------------------------------------------------------------------------
// Pass 1: contiguous z-axis forward FFT. Direct coalesced register loads
// (streaming __ldcs — input is read-once; protect L2 for F band output).
// fp16 out, band-filtered z. (Round-9 proven structure.)
// ---------------------------------------------------------------------------
__global__ void __launch_bounds__(256) fft256_p1(const float2* __restrict__ in,
                                                 __half2* __restrict__ out,
                                                 const float* tilt) {
    __shared__ float2 sm[8][288];
    __shared__ float2 tw[256];
    const int tid  = threadIdx.x;
    const int warp = tid >> 5;
    const int lane = tid & 31;
    const unsigned base = blockIdx.x * 2048u;

    float a = 128.0f * fabsf(sinf(*tilt));
    const int zlo = (int)floorf(126.0f - a);
    const int zhi = (int)ceilf(130.0f + a);

    {
        float s, c;
        sincospif((float)tid * (1.0f / 128.0f), &s, &c);
        tw[tid] = make_float2(c, -s);   // SIGN = -1
    }
    __syncthreads();

    float2 x[8];
    const float insgn = (lane & 1) ? -1.0f : 1.0f;
    {
        const float2* ip = in + base + (unsigned)warp * 256u;
#pragma unroll
        for (int r = 0; r < 8; r++) {
            float2 v = __ldcs(ip + r * 32 + lane);
            x[r] = make_float2(v.x * insgn, v.y * insgn);
        }
    }
    fft_core<-1>(x, lane, tw);

    const int k1tab[8] = {0, 4, 2, 6, 1, 5, 3, 7};
    const int p = (int)(__brev((unsigned)lane) >> 27);
#pragma unroll
    for (int r = 0; r < 8; r++) {
        int k = k1tab[r] + 8 * p;
        float sg = ((r >> 2) & 1) ? -1.0f : 1.0f;
        sm[warp][PIDX(k)] = make_float2(x[r].x * sg, x[r].y * sg);
    }
    __syncthreads();
#pragma unroll
    for (int idx = tid; idx < 1024; idx += 256) {
        int line = idx >> 7;
        int k = (idx & 127) * 2;
        if (k + 1 >= zlo && k <= zhi) {
            uint2 st = make_uint2(f2u(sm[line][PIDX(k)]), f2u(sm[line][PIDX(k + 1)]));
            *(uint2*)(out + base + (unsigned)line * 256u + k) = st;
        }
    }
}

// ---------------------------------------------------------------------------
// Strided-axis batched centered FFT: 16 lines/block, fp16 in, f32 smem,
// float4 staging with streaming loads (inputs are last-use in the chain).
// Shared layout idx(j,b) = j*17 + (b ^ (j>>4)).  (Round-9 proven config.)
// ZFILT: skip blocks whose z-range (z = line & 255) is outside sampled band.
// TRANSP: write f32 lines contiguously via __stcs (output never re-read).
// ---------------------------------------------------------------------------
template <int SIGN, bool INV, bool ZFILT, bool TRANSP, class TO>
__global__ void __launch_bounds__(256) fft256s(const __half2* __restrict__ in,
                                               TO* __restrict__ out,
                                               int lsi, const float* tilt) {
    __shared__ float2 sm[256 * 17];
    __shared__ float2 tw[256];
    const int tid  = threadIdx.x;
    const int warp = tid >> 5;
    const int lane = tid & 31;
    const unsigned l0 = blockIdx.x * 16u;

    if (ZFILT) {
        float a = 128.0f * fabsf(sinf(*tilt));
        int zlo = (int)floorf(126.0f - a);
        int zhi = (int)ceilf(130.0f + a);
        int z0 = (int)(l0 & 255u);
        if (z0 > zhi || z0 + 15 < zlo) return;
    }

    {
        float s, c;
        sincospif((float)tid * (1.0f / 128.0f), &s, &c);
        tw[tid] = make_float2(c, (float)SIGN * s);
    }

    const unsigned basei = ((l0 >> lsi) << (lsi + 8)) + (l0 & ((1u << lsi) - 1u));
    // float4 staging: 4 __half2 along b per load, streaming (read-once)
#pragma unroll
    for (int idx = tid; idx < 1024; idx += 256) {
        int bp = idx & 3;
        int j  = idx >> 2;
        int b  = 4 * bp;
        float4 v = __ldcs((const float4*)(in + basei + b + ((unsigned)j << lsi)));
        const unsigned* u = (const unsigned*)&v;
        int sw = j >> 4;
        int row = j * 17;
#pragma unroll
        for (int i = 0; i < 4; i++)
            sm[row + ((b + i) ^ sw)] = u2f2(u[i]);
    }
    __syncthreads();

    const float scale = INV ? (1.0f / 256.0f) : 1.0f;
    const float insgn = (lane & 1) ? -1.0f : 1.0f;
    const int k1tab[8] = {0, 4, 2, 6, 1, 5, 3, 7};
    const int p = (int)(__brev((unsigned)lane) >> 27);
#pragma unroll
    for (int c = 0; c < 2; c++) {
        const int line = warp + 8 * c;
        float2 x[8];
#pragma unroll
        for (int r = 0; r < 8; r++) {
            int j = r * 32 + lane;
            float2 v = sm[j * 17 + (line ^ (j >> 4))];
            x[r] = make_float2(v.x * insgn, v.y * insgn);
        }
        fft_core<SIGN>(x, lane, tw);
#pragma unroll
        for (int r = 0; r < 8; r++) {
            int k = k1tab[r] + 8 * p;
            float sg = ((r >> 2) & 1) ? -scale : scale;
            sm[k * 17 + (line ^ (k >> 4))] = make_float2(x[r].x * sg, x[r].y * sg);
        }
    }
    __syncthreads();

    if (TRANSP) {
        // f32 output, contiguous per line; streaming store (never re-read)
        const unsigned baseo = l0 << 8;
#pragma unroll
        for (int idx = tid; idx < 2048; idx += 256) {
            int kp = idx & 127;
            int b  = idx >> 7;
            int k  = 2 * kp;
            int sw = (k >> 4);
            float2 a = sm[k * 17 + (b ^ sw)];
            float2 c = sm[(k + 1) * 17 + (b ^ sw)];
            __stcs((float4*)((float2*)out + baseo + ((unsigned)b << 8) + k),
                   make_float4(a.x, a.y, c.x, c.y));
        }
    } else {
        // fp16 output, strided: float4 = 4 __half2 along b (normal store —
        // re-read by the next pass; want L2 residency)
#pragma unroll
        for (int idx = tid; idx < 1024; idx += 256) {
            int bp = idx & 3;
            int k  = idx >> 2;
            int b  = 4 * bp;
            int sw = (k >> 4);
            int row = k * 17;
            unsigned u[4];
#pragma unroll
            for (int i = 0; i < 4; i++)
                u[i] = f2u(sm[row + ((b + i) ^ sw)]);
            *(float4*)((__half2*)out + basei + b + ((unsigned)k << lsi)) = *(float4*)u;
        }
    }
}

// ---------------------------------------------------------------------------
// Fused Fourier-slice sampling + centered inverse FFT over iv.
// Warp owns line (m, iu); lanes walk iv (z-contiguous gathers).
// Interior fast path: 8 unpredicated scalar __ldg (proven floor form).
// Byte-identical to the 319.9µs round-9 version.
// ---------------------------------------------------------------------------
__global__ void __launch_bounds__(256) sample_fft_kernel(const __half2* __restrict__ F,
                                                         const float* __restrict__ theta,
                                                         const float* __restrict__ tilt,
                                                         __half2* __restrict__ T) {
    __shared__ float2 sm[8][288];
    __shared__ float2 tw[256];
    const int tid  = threadIdx.x;
    const int warp = tid >> 5;
    const int lane = tid & 31;

    {
        float s, c;
        sincospif((float)tid * (1.0f / 128.0f), &s, &c);
        tw[tid] = make_float2(c, s);  // SIGN = +1 (inverse)
    }
    __syncthreads();

    const int lid = blockIdx.x * 8 + warp;
    const int m  = lid >> 8;
    const int iu = lid & 255;

    float st, ct;
    sincosf(theta[m], &st, &ct);
    float sp, cp;
    sincosf(*tilt, &sp, &cp);

    const float u = (float)(iu - 128);
    const float evx = -st * cp, evy = ct * cp, evz = sp;
    const float bx = u * ct + 128.0f;
    const float by = u * st + 128.0f;
    const float bz = 128.0f;

    float2 x[8];
    const float insgn = (lane & 1) ? -1.0f : 1.0f;
#pragma unroll
    for (int r = 0; r < 8; r++) {
        float v = (float)(r * 32 + lane - 128);
        float px = fmaf(v, evx, bx);
        float py = fmaf(v, evy, by);
        float pz = fmaf(v, evz, bz);

        float fx0 = floorf(px), fy0 = floorf(py), fz0 = floorf(pz);
        float fx = px - fx0, fy = py - fy0, fz = pz - fz0;
        int x0 = (int)fx0, y0 = (int)fy0, z0 = (int)fz0;

        float2 acc = make_float2(0.0f, 0.0f);
        bool interior = ((unsigned)x0 <= 254u) && ((unsigned)y0 <= 254u) && ((unsigned)z0 <= 254u);
        bool anyhit = (x0 >= -1) && (x0 <= 255) && (y0 >= -1) && (y0 <= 255) &&
                      (z0 >= -1) && (z0 <= 255);
        if (interior) {
            const __half2* ptr = F + (((unsigned)x0 << 16) + ((unsigned)y0 << 8) + (unsigned)z0);
            float2 c000 = __half22float2(__ldg(ptr));
            float2 c001 = __half22float2(__ldg(ptr + 1));
            float2 c010 = __half22float2(__ldg(ptr + 256));
            float2 c011 = __half22float2(__ldg(ptr + 257));
            float2 c100 = __half22float2(__ldg(ptr + 65536));
            float2 c101 = __half22float2(__ldg(ptr + 65537));
            float2 c110 = __half22float2(__ldg(ptr + 65792));
            float2 c111 = __half22float2(__ldg(ptr + 65793));
            float gx = 1.0f - fx, gy = 1.0f - fy, gz = 1.0f - fz;
            float w00 = gx * gy, w01 = gx * fy, w10 = fx * gy, w11 = fx * fy;
            float w000 = w00 * gz, w001 = w00 * fz;
            float w010 = w01 * gz, w011 = w01 * fz;
            float w100 = w10 * gz, w101 = w10 * fz;
            float w110 = w11 * gz, w111 = w11 * fz;
            acc.x = w000 * c000.x + w001 * c001.x + w010 * c010.x + w011 * c011.x +
                    w100 * c100.x + w101 * c101.x + w110 * c110.x + w111 * c111.x;
            acc.y = w000 * c000.y + w001 * c001.y + w010 * c010.y + w011 * c011.y +
                    w100 * c100.y + w101 * c101.y + w110 * c110.y + w111 * c111.y;
        } else if (anyhit) {
#pragma unroll
            for (int dx = 0; dx < 2; dx++) {
                int X = x0 + dx;
                float wx = dx ? fx : (1.0f - fx);
#pragma unroll
                for (int dy = 0; dy < 2; dy++) {
                    int Y = y0 + dy;
                    float wy = wx * (dy ? fy : (1.0f - fy));
#pragma unroll
                    for (int dz = 0; dz < 2; dz++) {
                        int Z = z0 + dz;
                        float wz = wy * (dz ? fz : (1.0f - fz));
                        if ((unsigned)X < 256u && (unsigned)Y < 256u && (unsigned)Z < 256u) {
                            unsigned off = ((unsigned)X << 16) + ((unsigned)Y << 8) + (unsigned)Z;
                            float2 val = __half22float2(__ldg(&F[off]));
                            acc.x += wz * val.x;
                            acc.y += wz * val.y;
                        }
                    }
                }
            }
        }
        x[r] = make_float2(acc.x * insgn, acc.y * insgn);
    }

    fft_core<1>(x, lane, tw);

    const float scale = 1.0f / 256.0f;
    const int k1tab[8] = {0, 4, 2, 6, 1, 5, 3, 7};
    const int p = (int)(__brev((unsigned)lane) >> 27);
#pragma unroll
    for (int r = 0; r < 8; r++) {
        int k = k1tab[r] + 8 * p;
        float sg = ((r >> 2) & 1) ? -scale : scale;
        sm[warp][PIDX(k)] = make_float2(x[r].x * sg, x[r].y * sg);
    }
    __syncthreads();
    {
        const unsigned base = blockIdx.x * 2048u;
#pragma unroll
        for (int idx = tid; idx < 1024; idx += 256) {
            int line = idx >> 7;
            int k = (idx & 127) * 2;
            uint2 st = make_uint2(f2u(sm[line][PIDX(k)]), f2u(sm[line][PIDX(k + 1)]));
            *(uint2*)(T + base + (unsigned)line * 256u + k) = st;
        }
    }
}

// ---------------------------------------------------------------------------
extern "C" void kernel_launch(void* const* d_in, const int* in_sizes, int n_in,
                              void* d_out, int out_size) {
    const float2* w     = (const float2*)d_in[0];   // (256,256,256,2) f32
    const float*  theta = (const float*)d_in[1];    // (180,)
    const float*  tilt  = (const float*)d_in[2];    // scalar
    float2* out = (float2*)d_out;                   // (180,256,256,2) f32

    __half2 *F, *F2, *S;
    cudaGetSymbolAddress((void**)&F, g_Fh);
    cudaGetSymbolAddress((void**)&F2, g_F2h);
    cudaGetSymbolAddress((void**)&S, g_Sh);

    // Forward centered 3D FFT (ping-pong, fp16 intermediates):
    fft256_p1<<<8192, 256>>>(w, F, tilt);                                     // z
    fft256s<-1, false, true, false, __half2><<<4096, 256>>>(F, F2, 8, tilt);  // y
    fft256s<-1, false, true, false, __half2><<<4096, 256>>>(F2, F, 16, tilt); // x

    // Fused slice sampling + inverse FFT over iv -> T[m][iu][ka] (fp16)
    sample_fft_kernel<<<(MANG * 256) / 8, 256>>>(F, theta, tilt, S);

    // Inverse FFT over iu (stride 256 in T), transposed f32 store -> out
    fft256s<1, true, false, true, float2><<<(MANG * 256) / 16, 256>>>(S, out, 8, nullptr);
}

// round 15
// speedup vs baseline: 1.1022x; 1.0040x over previous
#include <cuda_runtime.h>
#include <cuda_fp16.h>

#define NV 256
#define MANG 180
#define PIDX(j) ((j) + ((j) >> 3))

// Scratch (static device globals — no runtime allocation)
__device__ __half2 g_Fh[NV * NV * NV];      // ping (67 MB)
__device__ __half2 g_F2h[NV * NV * NV];     // pong (67 MB)
__device__ __half2 g_Sh[MANG * NV * NV];    // slice intermediate T[m][iu][ka]

__device__ __forceinline__ float2 cmulf(float2 a, float2 b) {
    return make_float2(a.x * b.x - a.y * b.y, a.x * b.y + a.y * b.x);
}
__device__ __forceinline__ float2 u2f2(unsigned u) {
    __half2 h = *reinterpret_cast<__half2*>(&u);
    return __half22float2(h);
}
__device__ __forceinline__ unsigned f2u(float2 v) {
    __half2 h = __floats2half2_rn(v.x, v.y);
    return *reinterpret_cast<unsigned*>(&h);
}

// ---------------------------------------------------------------------------
// 256-pt FFT core: 8 regs/lane. radix-2^3 in regs + twiddle + radix-32 shuffle.
// On exit reg r, lane holds bin k = brev3(r) + 8*brev5(lane).
// ---------------------------------------------------------------------------
template <int SIGN>
__device__ __forceinline__ void fft_core(float2 x[8], int lane, const float2* tw) {
    const float SG = (float)SIGN;
    const float C7 = 0.70710678118654752f;
#define BTF(A, B, TR, TI_)                                         \
    {                                                              \
        float dr = (A).x - (B).x, di = (A).y - (B).y;              \
        (A).x += (B).x; (A).y += (B).y;                            \
        (B).x = dr * (TR) - di * (TI_);                            \
        (B).y = dr * (TI_) + di * (TR);                            \
    }
    BTF(x[0], x[4], 1.0f, 0.0f);
    BTF(x[1], x[5], C7, SG * C7);
    BTF(x[2], x[6], 0.0f, SG);
    BTF(x[3], x[7], -C7, SG * C7);
    BTF(x[0], x[2], 1.0f, 0.0f);
    BTF(x[1], x[3], 0.0f, SG);
    BTF(x[4], x[6], 1.0f, 0.0f);
    BTF(x[5], x[7], 0.0f, SG);
    BTF(x[0], x[1], 1.0f, 0.0f);
    BTF(x[2], x[3], 1.0f, 0.0f);
    BTF(x[4], x[5], 1.0f, 0.0f);
    BTF(x[6], x[7], 1.0f, 0.0f);
#undef BTF
    const int k1tab[8] = {0, 4, 2, 6, 1, 5, 3, 7};
#pragma unroll
    for (int r = 1; r < 8; r++)
        x[r] = cmulf(x[r], tw[(lane * k1tab[r]) & 255]);
#pragma unroll
    for (int s = 4; s >= 0; s--) {
        const int h = 1 << s;
        const int j = lane & (h - 1);
        const float2 w = tw[j << (7 - s)];
        const bool hi = (lane & h) != 0;
#pragma unroll
        for (int r = 0; r < 8; r++) {
            float2 o;
            o.x = __shfl_xor_sync(0xffffffffu, x[r].x, h);
            o.y = __shfl_xor_sync(0xffffffffu, x[r].y, h);
            if (hi) {
                float2 d = make_float2(o.x - x[r].x, o.y - x[r].y);
                x[r] = cmulf(d, w);
            } else {
                x[r].x += o.x;
                x[r].y += o.y;
            }
        }
    }
}

// ---------------------------------------------------------------------------
// Pass 1: contiguous z-axis forward FFT. Direct coalesced register loads
// (streaming __ldcs, issued BEFORE the tw-table sync so DRAM latency overlaps
// the barrier). fp16 out, band-filtered z.
// ---------------------------------------------------------------------------
__global__ void __launch_bounds__(256) fft256_p1(const float2* __restrict__ in,
                                                 __half2* __restrict__ out,
                                                 const float* tilt) {
    __shared__ float2 sm[8][288];
    __shared__ float2 tw[256];
    const int tid  = threadIdx.x;
    const int warp = tid >> 5;
    const int lane = tid & 31;
    const unsigned base = blockIdx.x * 2048u;

    float a = 128.0f * fabsf(sinf(*tilt));
    const int zlo = (int)floorf(126.0f - a);
    const int zhi = (int)ceilf(130.0f + a);

    {
        float s, c;
        sincospif((float)tid * (1.0f / 128.0f), &s, &c);
        tw[tid] = make_float2(c, -s);   // SIGN = -1
    }

    // gmem loads issued before the sync — they don't depend on tw
    float2 x[8];
    const float insgn = (lane & 1) ? -1.0f : 1.0f;
    {
        const float2* ip = in + base + (unsigned)warp * 256u;
#pragma unroll
        for (int r = 0; r < 8; r++) {
            float2 v = __ldcs(ip + r * 32 + lane);
            x[r] = make_float2(v.x * insgn, v.y * insgn);
        }
    }
    __syncthreads();   // tw writes visible before fft_core reads

    fft_core<-1>(x, lane, tw);

    const int k1tab[8] = {0, 4, 2, 6, 1, 5, 3, 7};
    const int p = (int)(__brev((unsigned)lane) >> 27);
#pragma unroll
    for (int r = 0; r < 8; r++) {
        int k = k1tab[r] + 8 * p;
        float sg = ((r >> 2) & 1) ? -1.0f : 1.0f;
        sm[warp][PIDX(k)] = make_float2(x[r].x * sg, x[r].y * sg);
    }
    __syncthreads();
#pragma unroll
    for (int idx = tid; idx < 1024; idx += 256) {
        int line = idx >> 7;
        int k = (idx & 127) * 2;
        if (k + 1 >= zlo && k <= zhi) {
            uint2 st = make_uint2(f2u(sm[line][PIDX(k)]), f2u(sm[line][PIDX(k + 1)]));
            *(uint2*)(out + base + (unsigned)line * 256u + k) = st;
        }
    }
}

// ---------------------------------------------------------------------------
// Strided-axis batched centered FFT: 16 lines/block, fp16 in, f32 smem,
// float4 staging with streaming loads (inputs are last-use in the chain).
// Shared layout idx(j,b) = j*17 + (b ^ (j>>4)).  (Proven champion config.)
// ZFILT: skip blocks whose z-range (z = line & 255) is outside sampled band.
// TRANSP: write f32 lines contiguously via __stcs (output never re-read).
// ---------------------------------------------------------------------------
template <int SIGN, bool INV, bool ZFILT, bool TRANSP, class TO>
__global__ void __launch_bounds__(256) fft256s(const __half2* __restrict__ in,
                                               TO* __restrict__ out,
                                               int lsi, const float* tilt) {
    __shared__ float2 sm[256 * 17];
    __shared__ float2 tw[256];
    const int tid  = threadIdx.x;
    const int warp = tid >> 5;
    const int lane = tid & 31;
    const unsigned l0 = blockIdx.x * 16u;

    if (ZFILT) {
        float a = 128.0f * fabsf(sinf(*tilt));
        int zlo = (int)floorf(126.0f - a);
        int zhi = (int)ceilf(130.0f + a);
        int z0 = (int)(l0 & 255u);
        if (z0 > zhi || z0 + 15 < zlo) return;
    }

    {
        float s, c;
        sincospif((float)tid * (1.0f / 128.0f), &s, &c);
        tw[tid] = make_float2(c, (float)SIGN * s);
    }

    const unsigned basei = ((l0 >> lsi) << (lsi + 8)) + (l0 & ((1u << lsi) - 1u));
    // float4 staging: 4 __half2 along b per load, streaming (read-once)
#pragma unroll
    for (int idx = tid; idx < 1024; idx += 256) {
        int bp = idx & 3;
        int j  = idx >> 2;
        int b  = 4 * bp;
        float4 v = __ldcs((const float4*)(in + basei + b + ((unsigned)j << lsi)));
        const unsigned* u = (const unsigned*)&v;
        int sw = j >> 4;
        int row = j * 17;
#pragma unroll
        for (int i = 0; i < 4; i++)
            sm[row + ((b + i) ^ sw)] = u2f2(u[i]);
    }
    __syncthreads();

    const float scale = INV ? (1.0f / 256.0f) : 1.0f;
    const float insgn = (lane & 1) ? -1.0f : 1.0f;
    const int k1tab[8] = {0, 4, 2, 6, 1, 5, 3, 7};
    const int p = (int)(__brev((unsigned)lane) >> 27);
#pragma unroll
    for (int c = 0; c < 2; c++) {
        const int line = warp + 8 * c;
        float2 x[8];
#pragma unroll
        for (int r = 0; r < 8; r++) {
            int j = r * 32 + lane;
            float2 v = sm[j * 17 + (line ^ (j >> 4))];
            x[r] = make_float2(v.x * insgn, v.y * insgn);
        }
        fft_core<SIGN>(x, lane, tw);
#pragma unroll
        for (int r = 0; r < 8; r++) {
            int k = k1tab[r] + 8 * p;
            float sg = ((r >> 2) & 1) ? -scale : scale;
            sm[k * 17 + (line ^ (k >> 4))] = make_float2(x[r].x * sg, x[r].y * sg);
        }
    }
    __syncthreads();

    if (TRANSP) {
        // f32 output, contiguous per line; streaming store (never re-read)
        const unsigned baseo = l0 << 8;
#pragma unroll
        for (int idx = tid; idx < 2048; idx += 256) {
            int kp = idx & 127;
            int b  = idx >> 7;
            int k  = 2 * kp;
            int sw = (k >> 4);
            float2 a = sm[k * 17 + (b ^ sw)];
            float2 c = sm[(k + 1) * 17 + (b ^ sw)];
            __stcs((float4*)((float2*)out + baseo + ((unsigned)b << 8) + k),
                   make_float4(a.x, a.y, c.x, c.y));
        }
    } else {
        // fp16 output, strided: float4 = 4 __half2 along b (normal store —
        // re-read by the next pass; want L2 residency)
#pragma unroll
        for (int idx = tid; idx < 1024; idx += 256) {
            int bp = idx & 3;
            int k  = idx >> 2;
            int b  = 4 * bp;
            int sw = (k >> 4);
            int row = k * 17;
            unsigned u[4];
#pragma unroll
            for (int i = 0; i < 4; i++)
                u[i] = f2u(sm[row + ((b + i) ^ sw)]);
            *(float4*)((__half2*)out + basei + b + ((unsigned)k << lsi)) = *(float4*)u;
        }
    }
}

// ---------------------------------------------------------------------------
// Fused Fourier-slice sampling + centered inverse FFT over iv.
// Warp owns line (m, iu); lanes walk iv (z-contiguous gathers).
// Interior fast path: 8 unpredicated scalar __ldg (proven floor form).
// Sync moved to just before fft_core — warps start gathering immediately.
// ---------------------------------------------------------------------------
__global__ void __launch_bounds__(256) sample_fft_kernel(const __half2* __restrict__ F,
                                                         const float* __restrict__ theta,
                                                         const float* __restrict__ tilt,
                                                         __half2* __restrict__ T) {
    __shared__ float2 sm[8][288];
    __shared__ float2 tw[256];
    const int tid  = threadIdx.x;
    const int warp = tid >> 5;
    const int lane = tid & 31;

    {
        float s, c;
        sincospif((float)tid * (1.0f / 128.0f), &s, &c);
        tw[tid] = make_float2(c, s);  // SIGN = +1 (inverse)
    }

    const int lid = blockIdx.x * 8 + warp;
    const int m  = lid >> 8;
    const int iu = lid & 255;

    float st, ct;
    sincosf(theta[m], &st, &ct);
    float sp, cp;
    sincosf(*tilt, &sp, &cp);

    const float u = (float)(iu - 128);
    const float evx = -st * cp, evy = ct * cp, evz = sp;
    const float bx = u * ct + 128.0f;
    const float by = u * st + 128.0f;
    const float bz = 128.0f;

    float2 x[8];
    const float insgn = (lane & 1) ? -1.0f : 1.0f;
#pragma unroll
    for (int r = 0; r < 8; r++) {
        float v = (float)(r * 32 + lane - 128);
        float px = fmaf(v, evx, bx);
        float py = fmaf(v, evy, by);
        float pz = fmaf(v, evz, bz);

        float fx0 = floorf(px), fy0 = floorf(py), fz0 = floorf(pz);
        float fx = px - fx0, fy = py - fy0, fz = pz - fz0;
        int x0 = (int)fx0, y0 = (int)fy0, z0 = (int)fz0;

        float2 acc = make_float2(0.0f, 0.0f);
        bool interior = ((unsigned)x0 <= 254u) && ((unsigned)y0 <= 254u) && ((unsigned)z0 <= 254u);
        bool anyhit = (x0 >= -1) && (x0 <= 255) && (y0 >= -1) && (y0 <= 255) &&
                      (z0 >= -1) && (z0 <= 255);
        if (interior) {
            const __half2* ptr = F + (((unsigned)x0 << 16) + ((unsigned)y0 << 8) + (unsigned)z0);
            float2 c000 = __half22float2(__ldg(ptr));
            float2 c001 = __half22float2(__ldg(ptr + 1));
            float2 c010 = __half22float2(__ldg(ptr + 256));
            float2 c011 = __half22float2(__ldg(ptr + 257));
            float2 c100 = __half22float2(__ldg(ptr + 65536));
            float2 c101 = __half22float2(__ldg(ptr + 65537));
            float2 c110 = __half22float2(__ldg(ptr + 65792));
            float2 c111 = __half22float2(__ldg(ptr + 65793));
            float gx = 1.0f - fx, gy = 1.0f - fy, gz = 1.0f - fz;
            float w00 = gx * gy, w01 = gx * fy, w10 = fx * gy, w11 = fx * fy;
            float w000 = w00 * gz, w001 = w00 * fz;
            float w010 = w01 * gz, w011 = w01 * fz;
            float w100 = w10 * gz, w101 = w10 * fz;
            float w110 = w11 * gz, w111 = w11 * fz;
            acc.x = w000 * c000.x + w001 * c001.x + w010 * c010.x + w011 * c011.x +
                    w100 * c100.x + w101 * c101.x + w110 * c110.x + w111 * c111.x;
            acc.y = w000 * c000.y + w001 * c001.y + w010 * c010.y + w011 * c011.y +
                    w100 * c100.y + w101 * c101.y + w110 * c110.y + w111 * c111.y;
        } else if (anyhit) {
#pragma unroll
            for (int dx = 0; dx < 2; dx++) {
                int X = x0 + dx;
                float wx = dx ? fx : (1.0f - fx);
#pragma unroll
                for (int dy = 0; dy < 2; dy++) {
                    int Y = y0 + dy;
                    float wy = wx * (dy ? fy : (1.0f - fy));
#pragma unroll
                    for (int dz = 0; dz < 2; dz++) {
                        int Z = z0 + dz;
                        float wz = wy * (dz ? fz : (1.0f - fz));
                        if ((unsigned)X < 256u && (unsigned)Y < 256u && (unsigned)Z < 256u) {
                            unsigned off = ((unsigned)X << 16) + ((unsigned)Y << 8) + (unsigned)Z;
                            float2 val = __half22float2(__ldg(&F[off]));
                            acc.x += wz * val.x;
                            acc.y += wz * val.y;
                        }
                    }
                }
            }
        }
        x[r] = make_float2(acc.x * insgn, acc.y * insgn);
    }

    __syncthreads();   // tw writes visible before fft_core reads

    fft_core<1>(x, lane, tw);

    const float scale = 1.0f / 256.0f;
    const int k1tab[8] = {0, 4, 2, 6, 1, 5, 3, 7};
    const int p = (int)(__brev((unsigned)lane) >> 27);
#pragma unroll
    for (int r = 0; r < 8; r++) {
        int k = k1tab[r] + 8 * p;
        float sg = ((r >> 2) & 1) ? -scale : scale;
        sm[warp][PIDX(k)] = make_float2(x[r].x * sg, x[r].y * sg);
    }
    __syncthreads();
    {
        const unsigned base = blockIdx.x * 2048u;
#pragma unroll
        for (int idx = tid; idx < 1024; idx += 256) {
            int line = idx >> 7;
            int k = (idx & 127) * 2;
            uint2 st = make_uint2(f2u(sm[line][PIDX(k)]), f2u(sm[line][PIDX(k + 1)]));
            *(uint2*)(T + base + (unsigned)line * 256u + k) = st;
        }
    }
}

// ---------------------------------------------------------------------------
extern "C" void kernel_launch(void* const* d_in, const int* in_sizes, int n_in,
                              void* d_out, int out_size) {
    const float2* w     = (const float2*)d_in[0];   // (256,256,256,2) f32
    const float*  theta = (const float*)d_in[1];    // (180,)
    const float*  tilt  = (const float*)d_in[2];    // scalar
    float2* out = (float2*)d_out;                   // (180,256,256,2) f32

    __half2 *F, *F2, *S;
    cudaGetSymbolAddress((void**)&F, g_Fh);
    cudaGetSymbolAddress((void**)&F2, g_F2h);
    cudaGetSymbolAddress((void**)&S, g_Sh);

    // Forward centered 3D FFT (ping-pong, fp16 intermediates):
    fft256_p1<<<8192, 256>>>(w, F, tilt);                                     // z
    fft256s<-1, false, true, false, __half2><<<4096, 256>>>(F, F2, 8, tilt);  // y
    fft256s<-1, false, true, false, __half2><<<4096, 256>>>(F2, F, 16, tilt); // x

    // Fused slice sampling + inverse FFT over iv -> T[m][iu][ka] (fp16)
    sample_fft_kernel<<<(MANG * 256) / 8, 256>>>(F, theta, tilt, S);

    // Inverse FFT over iu (stride 256 in T), transposed f32 store -> out
    fft256s<1, true, false, true, float2><<<(MANG * 256) / 16, 256>>>(S, out, 8, nullptr);
}

// round 16
// speedup vs baseline: 1.1031x; 1.0008x over previous
#include <cuda_runtime.h>
#include <cuda_fp16.h>

#define NV 256
#define MANG 180
#define PIDX(j) ((j) + ((j) >> 3))

// Scratch (static device globals — no runtime allocation)
__device__ __half2 g_Fh[NV * NV * NV];      // ping (67 MB)
__device__ __half2 g_F2h[NV * NV * NV];     // pong (67 MB)
__device__ __half2 g_Sh[MANG * NV * NV];    // slice intermediate T[m][iu][ka]

__device__ __forceinline__ float2 cmulf(float2 a, float2 b) {
    return make_float2(a.x * b.x - a.y * b.y, a.x * b.y + a.y * b.x);
}
__device__ __forceinline__ float2 u2f2(unsigned u) {
    __half2 h = *reinterpret_cast<__half2*>(&u);
    return __half22float2(h);
}
__device__ __forceinline__ unsigned f2u(float2 v) {
    __half2 h = __floats2half2_rn(v.x, v.y);
    return *reinterpret_cast<unsigned*>(&h);
}

// ---------------------------------------------------------------------------
// 256-pt FFT core: 8 regs/lane. radix-2^3 in regs + twiddle + radix-32 shuffle.
// On exit reg r, lane holds bin k = brev3(r) + 8*brev5(lane).
// ---------------------------------------------------------------------------
template <int SIGN>
__device__ __forceinline__ void fft_core(float2 x[8], int lane, const float2* tw) {
    const float SG = (float)SIGN;
    const float C7 = 0.70710678118654752f;
#define BTF(A, B, TR, TI_)                                         \
    {                                                              \
        float dr = (A).x - (B).x, di = (A).y - (B).y;              \
        (A).x += (B).x; (A).y += (B).y;                            \
        (B).x = dr * (TR) - di * (TI_);                            \
        (B).y = dr * (TI_) + di * (TR);                            \
    }
    BTF(x[0], x[4], 1.0f, 0.0f);
    BTF(x[1], x[5], C7, SG * C7);
    BTF(x[2], x[6], 0.0f, SG);
    BTF(x[3], x[7], -C7, SG * C7);
    BTF(x[0], x[2], 1.0f, 0.0f);
    BTF(x[1], x[3], 0.0f, SG);
    BTF(x[4], x[6], 1.0f, 0.0f);
    BTF(x[5], x[7], 0.0f, SG);
    BTF(x[0], x[1], 1.0f, 0.0f);
    BTF(x[2], x[3], 1.0f, 0.0f);
    BTF(x[4], x[5], 1.0f, 0.0f);
    BTF(x[6], x[7], 1.0f, 0.0f);
#undef BTF
    const int k1tab[8] = {0, 4, 2, 6, 1, 5, 3, 7};
#pragma unroll
    for (int r = 1; r < 8; r++)
        x[r] = cmulf(x[r], tw[(lane * k1tab[r]) & 255]);
#pragma unroll
    for (int s = 4; s >= 0; s--) {
        const int h = 1 << s;
        const int j = lane & (h - 1);
        const float2 w = tw[j << (7 - s)];
        const bool hi = (lane & h) != 0;
#pragma unroll
        for (int r = 0; r < 8; r++) {
            float2 o;
            o.x = __shfl_xor_sync(0xffffffffu, x[r].x, h);
            o.y = __shfl_xor_sync(0xffffffffu, x[r].y, h);
            if (hi) {
                float2 d = make_float2(o.x - x[r].x, o.y - x[r].y);
                x[r] = cmulf(d, w);
            } else {
                x[r].x += o.x;
                x[r].y += o.y;
            }
        }
    }
}

// ---------------------------------------------------------------------------
// Pass 1: contiguous z-axis forward FFT. Direct coalesced register loads
// (streaming __ldcs, issued BEFORE the tw-table sync so DRAM latency overlaps
// the barrier). fp16 out, band-filtered z.
// ---------------------------------------------------------------------------
__global__ void __launch_bounds__(256) fft256_p1(const float2* __restrict__ in,
                                                 __half2* __restrict__ out,
                                                 const float* tilt) {
    __shared__ float2 sm[8][288];
    __shared__ float2 tw[256];
    const int tid  = threadIdx.x;
    const int warp = tid >> 5;
    const int lane = tid & 31;
    const unsigned base = blockIdx.x * 2048u;

    float a = 128.0f * fabsf(sinf(*tilt));
    const int zlo = (int)floorf(126.0f - a);
    const int zhi = (int)ceilf(130.0f + a);

    {
        float s, c;
        sincospif((float)tid * (1.0f / 128.0f), &s, &c);
        tw[tid] = make_float2(c, -s);   // SIGN = -1
    }

    // gmem loads issued before the sync — they don't depend on tw
    float2 x[8];
    const float insgn = (lane & 1) ? -1.0f : 1.0f;
    {
        const float2* ip = in + base + (unsigned)warp * 256u;
#pragma unroll
        for (int r = 0; r < 8; r++) {
            float2 v = __ldcs(ip + r * 32 + lane);
            x[r] = make_float2(v.x * insgn, v.y * insgn);
        }
    }
    __syncthreads();   // tw writes visible before fft_core reads

    fft_core<-1>(x, lane, tw);

    const int k1tab[8] = {0, 4, 2, 6, 1, 5, 3, 7};
    const int p = (int)(__brev((unsigned)lane) >> 27);
#pragma unroll
    for (int r = 0; r < 8; r++) {
        int k = k1tab[r] + 8 * p;
        float sg = ((r >> 2) & 1) ? -1.0f : 1.0f;
        sm[warp][PIDX(k)] = make_float2(x[r].x * sg, x[r].y * sg);
    }
    __syncthreads();
#pragma unroll
    for (int idx = tid; idx < 1024; idx += 256) {
        int line = idx >> 7;
        int k = (idx & 127) * 2;
        if (k + 1 >= zlo && k <= zhi) {
            uint2 st = make_uint2(f2u(sm[line][PIDX(k)]), f2u(sm[line][PIDX(k + 1)]));
            *(uint2*)(out + base + (unsigned)line * 256u + k) = st;
        }
    }
}

// ---------------------------------------------------------------------------
// Strided-axis batched centered FFT: 16 lines/block, fp16 in, f32 smem.
// Staging loads batched into registers FIRST (MLP=4) before the MUFU-heavy
// twiddle build, then converted/scattered to smem.
// Shared layout idx(j,b) = j*17 + (b ^ (j>>4)).
// ZFILT: skip blocks whose z-range (z = line & 255) is outside sampled band.
// TRANSP: write f32 lines contiguously via __stcs (output never re-read).
// ---------------------------------------------------------------------------
template <int SIGN, bool INV, bool ZFILT, bool TRANSP, class TO>
__global__ void __launch_bounds__(256) fft256s(const __half2* __restrict__ in,
                                               TO* __restrict__ out,
                                               int lsi, const float* tilt) {
    __shared__ float2 sm[256 * 17];
    __shared__ float2 tw[256];
    const int tid  = threadIdx.x;
    const int warp = tid >> 5;
    const int lane = tid & 31;
    const unsigned l0 = blockIdx.x * 16u;

    if (ZFILT) {
        float a = 128.0f * fabsf(sinf(*tilt));
        int zlo = (int)floorf(126.0f - a);
        int zhi = (int)ceilf(130.0f + a);
        int z0 = (int)(l0 & 255u);
        if (z0 > zhi || z0 + 15 < zlo) return;
    }

    const unsigned basei = ((l0 >> lsi) << (lsi + 8)) + (l0 & ((1u << lsi) - 1u));

    // ---- batched staging loads: all 4 float4 in flight before tw build ----
    float4 vreg[4];
#pragma unroll
    for (int t = 0; t < 4; t++) {
        int idx = tid + t * 256;
        int bp = idx & 3;
        int j  = idx >> 2;
        vreg[t] = __ldcs((const float4*)(in + basei + 4 * bp + ((unsigned)j << lsi)));
    }

    // twiddle build overlaps the outstanding loads
    {
        float s, c;
        sincospif((float)tid * (1.0f / 128.0f), &s, &c);
        tw[tid] = make_float2(c, (float)SIGN * s);
    }

    // convert + scatter to smem
#pragma unroll
    for (int t = 0; t < 4; t++) {
        int idx = tid + t * 256;
        int bp = idx & 3;
        int j  = idx >> 2;
        int b  = 4 * bp;
        const unsigned* u = (const unsigned*)&vreg[t];
        int sw = j >> 4;
        int row = j * 17;
#pragma unroll
        for (int i = 0; i < 4; i++)
            sm[row + ((b + i) ^ sw)] = u2f2(u[i]);
    }
    __syncthreads();

    const float scale = INV ? (1.0f / 256.0f) : 1.0f;
    const float insgn = (lane & 1) ? -1.0f : 1.0f;
    const int k1tab[8] = {0, 4, 2, 6, 1, 5, 3, 7};
    const int p = (int)(__brev((unsigned)lane) >> 27);
#pragma unroll
    for (int c = 0; c < 2; c++) {
        const int line = warp + 8 * c;
        float2 x[8];
#pragma unroll
        for (int r = 0; r < 8; r++) {
            int j = r * 32 + lane;
            float2 v = sm[j * 17 + (line ^ (j >> 4))];
            x[r] = make_float2(v.x * insgn, v.y * insgn);
        }
        fft_core<SIGN>(x, lane, tw);
#pragma unroll
        for (int r = 0; r < 8; r++) {
            int k = k1tab[r] + 8 * p;
            float sg = ((r >> 2) & 1) ? -scale : scale;
            sm[k * 17 + (line ^ (k >> 4))] = make_float2(x[r].x * sg, x[r].y * sg);
        }
    }
    __syncthreads();

    if (TRANSP) {
        // f32 output, contiguous per line; streaming store (never re-read)
        const unsigned baseo = l0 << 8;
#pragma unroll
        for (int idx = tid; idx < 2048; idx += 256) {
            int kp = idx & 127;
            int b  = idx >> 7;
            int k  = 2 * kp;
            int sw = (k >> 4);
            float2 a = sm[k * 17 + (b ^ sw)];
            float2 c = sm[(k + 1) * 17 + (b ^ sw)];
            __stcs((float4*)((float2*)out + baseo + ((unsigned)b << 8) + k),
                   make_float4(a.x, a.y, c.x, c.y));
        }
    } else {
        // fp16 output, strided: float4 = 4 __half2 along b (normal store —
        // re-read by the next pass; want L2 residency)
#pragma unroll
        for (int idx = tid; idx < 1024; idx += 256) {
            int bp = idx & 3;
            int k  = idx >> 2;
            int b  = 4 * bp;
            int sw = (k >> 4);
            int row = k * 17;
            unsigned u[4];
#pragma unroll
            for (int i = 0; i < 4; i++)
                u[i] = f2u(sm[row + ((b + i) ^ sw)]);
            *(float4*)((__half2*)out + basei + b + ((unsigned)k << lsi)) = *(float4*)u;
        }
    }
}

// ---------------------------------------------------------------------------
// Fused Fourier-slice sampling + centered inverse FFT over iv.
// Warp owns line (m, iu); lanes walk iv (z-contiguous gathers).
// Interior fast path: 8 unpredicated scalar __ldg (proven floor form).
// Sync deferred to just before fft_core (tw ordering only).
// ---------------------------------------------------------------------------
__global__ void __launch_bounds__(256) sample_fft_kernel(const __half2* __restrict__ F,
                                                         const float* __restrict__ theta,
                                                         const float* __restrict__ tilt,
                                                         __half2* __restrict__ T) {
    __shared__ float2 sm[8][288];
    __shared__ float2 tw[256];
    const int tid  = threadIdx.x;
    const int warp = tid >> 5;
    const int lane = tid & 31;

    {
        float s, c;
        sincospif((float)tid * (1.0f / 128.0f), &s, &c);
        tw[tid] = make_float2(c, s);  // SIGN = +1 (inverse)
    }

    const int lid = blockIdx.x * 8 + warp;
    const int m  = lid >> 8;
    const int iu = lid & 255;

    float st, ct;
    sincosf(theta[m], &st, &ct);
    float sp, cp;
    sincosf(*tilt, &sp, &cp);

    const float u = (float)(iu - 128);
    const float evx = -st * cp, evy = ct * cp, evz = sp;
    const float bx = u * ct + 128.0f;
    const float by = u * st + 128.0f;
    const float bz = 128.0f;

    float2 x[8];
    const float insgn = (lane & 1) ? -1.0f : 1.0f;
#pragma unroll
    for (int r = 0; r < 8; r++) {
        float v = (float)(r * 32 + lane - 128);
        float px = fmaf(v, evx, bx);
        float py = fmaf(v, evy, by);
        float pz = fmaf(v, evz, bz);

        float fx0 = floorf(px), fy0 = floorf(py), fz0 = floorf(pz);
        float fx = px - fx0, fy = py - fy0, fz = pz - fz0;
        int x0 = (int)fx0, y0 = (int)fy0, z0 = (int)fz0;

        float2 acc = make_float2(0.0f, 0.0f);
        bool interior = ((unsigned)x0 <= 254u) && ((unsigned)y0 <= 254u) && ((unsigned)z0 <= 254u);
        bool anyhit = (x0 >= -1) && (x0 <= 255) && (y0 >= -1) && (y0 <= 255) &&
                      (z0 >= -1) && (z0 <= 255);
        if (interior) {
            const __half2* ptr = F + (((unsigned)x0 << 16) + ((unsigned)y0 << 8) + (unsigned)z0);
            float2 c000 = __half22float2(__ldg(ptr));
            float2 c001 = __half22float2(__ldg(ptr + 1));
            float2 c010 = __half22float2(__ldg(ptr + 256));
            float2 c011 = __half22float2(__ldg(ptr + 257));
            float2 c100 = __half22float2(__ldg(ptr + 65536));
            float2 c101 = __half22float2(__ldg(ptr + 65537));
            float2 c110 = __half22float2(__ldg(ptr + 65792));
            float2 c111 = __half22float2(__ldg(ptr + 65793));
            float gx = 1.0f - fx, gy = 1.0f - fy, gz = 1.0f - fz;
            float w00 = gx * gy, w01 = gx * fy, w10 = fx * gy, w11 = fx * fy;
            float w000 = w00 * gz, w001 = w00 * fz;
            float w010 = w01 * gz, w011 = w01 * fz;
            float w100 = w10 * gz, w101 = w10 * fz;
            float w110 = w11 * gz, w111 = w11 * fz;
            acc.x = w000 * c000.x + w001 * c001.x + w010 * c010.x + w011 * c011.x +
                    w100 * c100.x + w101 * c101.x + w110 * c110.x + w111 * c111.x;
            acc.y = w000 * c000.y + w001 * c001.y + w010 * c010.y + w011 * c011.y +
                    w100 * c100.y + w101 * c101.y + w110 * c110.y + w111 * c111.y;
        } else if (anyhit) {
#pragma unroll
            for (int dx = 0; dx < 2; dx++) {
                int X = x0 + dx;
                float wx = dx ? fx : (1.0f - fx);
#pragma unroll
                for (int dy = 0; dy < 2; dy++) {
                    int Y = y0 + dy;
                    float wy = wx * (dy ? fy : (1.0f - fy));
#pragma unroll
                    for (int dz = 0; dz < 2; dz++) {
                        int Z = z0 + dz;
                        float wz = wy * (dz ? fz : (1.0f - fz));
                        if ((unsigned)X < 256u && (unsigned)Y < 256u && (unsigned)Z < 256u) {
                            unsigned off = ((unsigned)X << 16) + ((unsigned)Y << 8) + (unsigned)Z;
                            float2 val = __half22float2(__ldg(&F[off]));
                            acc.x += wz * val.x;
                            acc.y += wz * val.y;
                        }
                    }
                }
            }
        }
        x[r] = make_float2(acc.x * insgn, acc.y * insgn);
    }

    __syncthreads();   // tw writes visible before fft_core reads

    fft_core<1>(x, lane, tw);

    const float scale = 1.0f / 256.0f;
    const int k1tab[8] = {0, 4, 2, 6, 1, 5, 3, 7};
    const int p = (int)(__brev((unsigned)lane) >> 27);
#pragma unroll
    for (int r = 0; r < 8; r++) {
        int k = k1tab[r] + 8 * p;
        float sg = ((r >> 2) & 1) ? -scale : scale;
        sm[warp][PIDX(k)] = make_float2(x[r].x * sg, x[r].y * sg);
    }
    __syncthreads();
    {
        const unsigned base = blockIdx.x * 2048u;
#pragma unroll
        for (int idx = tid; idx < 1024; idx += 256) {
            int line = idx >> 7;
            int k = (idx & 127) * 2;
            uint2 st = make_uint2(f2u(sm[line][PIDX(k)]), f2u(sm[line][PIDX(k + 1)]));
            *(uint2*)(T + base + (unsigned)line * 256u + k) = st;
        }
    }
}

// ---------------------------------------------------------------------------
extern "C" void kernel_launch(void* const* d_in, const int* in_sizes, int n_in,
                              void* d_out, int out_size) {
    const float2* w     = (const float2*)d_in[0];   // (256,256,256,2) f32
    const float*  theta = (const float*)d_in[1];    // (180,)
    const float*  tilt  = (const float*)d_in[2];    // scalar
    float2* out = (float2*)d_out;                   // (180,256,256,2) f32

    __half2 *F, *F2, *S;
    cudaGetSymbolAddress((void**)&F, g_Fh);
    cudaGetSymbolAddress((void**)&F2, g_F2h);
    cudaGetSymbolAddress((void**)&S, g_Sh);

    // Forward centered 3D FFT (ping-pong, fp16 intermediates):
    fft256_p1<<<8192, 256>>>(w, F, tilt);                                     // z
    fft256s<-1, false, true, false, __half2><<<4096, 256>>>(F, F2, 8, tilt);  // y
    fft256s<-1, false, true, false, __half2><<<4096, 256>>>(F2, F, 16, tilt); // x

    // Fused slice sampling + inverse FFT over iv -> T[m][iu][ka] (fp16)
    sample_fft_kernel<<<(MANG * 256) / 8, 256>>>(F, theta, tilt, S);

    // Inverse FFT over iu (stride 256 in T), transposed f32 store -> out
    fft256s<1, true, false, true, float2><<<(MANG * 256) / 16, 256>>>(S, out, 8, nullptr);
}